// round 12
// baseline (speedup 1.0000x reference)
#include <cuda_runtime.h>
#include <cstdint>

// Problem constants
#define Bsz 32
#define Lsz 4096
#define Isz 128
#define Hsz 256
#define Osz 128
#define NDELAY 5      // delay line length (DELAY+1)

// Scratch (static device globals: allocation-free per harness rules)
__device__ float g_xz[Bsz * Lsz * Hsz];
__device__ float g_xh[Bsz * Lsz * Hsz];
__device__ float g_hs[Bsz * Lsz * Hsz];

// ---------------------------------------------------------------------------
// fp32 tiled GEMM with bias, packed f32x2 accumulation.
// C[M,N] = A[M,K] @ B[K,N] + bias[N]; 64x64 tile, 256 threads, 4x4 micro.
// ---------------------------------------------------------------------------
__global__ void __launch_bounds__(256) gemm_bias(
    const float* __restrict__ A, const float* __restrict__ Bm,
    const float* __restrict__ bias, float* __restrict__ C,
    int M, int K, int N)
{
    __shared__ float sA[64][68];
    __shared__ float sB[64][68];

    const int m0  = blockIdx.x << 6;
    const int n0  = blockIdx.y << 6;
    const int tid = threadIdx.x;
    const int tx  = tid & 15;
    const int ty  = tid >> 4;

    uint64_t acc01[4], acc23[4];   // packed (col0,col1) / (col2,col3) per row
#pragma unroll
    for (int i = 0; i < 4; i++) { acc01[i] = 0; acc23[i] = 0; }

    for (int kk = 0; kk < K; kk += 64) {
#pragma unroll
        for (int i = 0; i < 4; i++) {
            int lin = tid + (i << 8);
            int r   = lin >> 4;
            int c   = (lin & 15) << 2;
            *(float4*)&sA[r][c] = *(const float4*)&A[(size_t)(m0 + r) * K + kk + c];
            *(float4*)&sB[r][c] = *(const float4*)&Bm[(size_t)(kk + r) * N + n0 + c];
        }
        __syncthreads();

#pragma unroll 16
        for (int k = 0; k < 64; k++) {
            ulonglong2 bb = *(const ulonglong2*)&sB[k][tx << 2];
#pragma unroll
            for (int i = 0; i < 4; i++) {
                float a = sA[(ty << 2) + i][k];
                uint64_t aa;
                asm("mov.b64 %0, {%1, %1};" : "=l"(aa) : "f"(a));
                asm("fma.rn.f32x2 %0, %1, %2, %0;" : "+l"(acc01[i]) : "l"(aa), "l"(bb.x));
                asm("fma.rn.f32x2 %0, %1, %2, %0;" : "+l"(acc23[i]) : "l"(aa), "l"(bb.y));
            }
        }
        __syncthreads();
    }

    float4 bb = *(const float4*)&bias[n0 + (tx << 2)];
#pragma unroll
    for (int i = 0; i < 4; i++) {
        float c0, c1, c2, c3;
        asm("mov.b64 {%0, %1}, %2;" : "=f"(c0), "=f"(c1) : "l"(acc01[i]));
        asm("mov.b64 {%0, %1}, %2;" : "=f"(c2), "=f"(c3) : "l"(acc23[i]));
        float4 o;
        o.x = c0 + bb.x; o.y = c1 + bb.y; o.z = c2 + bb.z; o.w = c3 + bb.w;
        *(float4*)&C[(size_t)(m0 + (ty << 2) + i) * N + n0 + (tx << 2)] = o;
    }
}

// ---------------------------------------------------------------------------
// Fast-math helpers (ex2/rcp approx: rel err ~1e-7)
// ---------------------------------------------------------------------------
__device__ __forceinline__ float ex2_fast(float x) {
    float r; asm("ex2.approx.f32 %0, %1;" : "=f"(r) : "f"(x)); return r;
}
__device__ __forceinline__ float rcp_fast(float x) {
    float r; asm("rcp.approx.f32 %0, %1;" : "=f"(r) : "f"(x)); return r;
}
__device__ __forceinline__ float sigmoid_fast(float x) {
    return rcp_fast(1.f + ex2_fast(-1.4426950408889634f * x));
}
__device__ __forceinline__ float tanh_fast(float x) {
    float e = ex2_fast(2.885390081777927f * x);
    return (e - 1.f) * rcp_fast(e + 1.f);
}

// Packed f32x2 dot over 64 floats; all lanes read the SAME addresses
// (whole-warp broadcast -> conflict-free, 1 wavefront per LDS.128).
__device__ __forceinline__ float dot64_bcast(const float* p, const uint64_t* w) {
    const ulonglong2* v = (const ulonglong2*)p;
    uint64_t a0 = 0, a1 = 0, a2 = 0, a3 = 0;
#pragma unroll
    for (int j = 0; j < 8; j++) {
        ulonglong2 t = v[j];
        asm("fma.rn.f32x2 %0, %1, %2, %0;" : "+l"(a0) : "l"(t.x), "l"(w[2*j]));
        asm("fma.rn.f32x2 %0, %1, %2, %0;" : "+l"(a1) : "l"(t.y), "l"(w[2*j+1]));
    }
#pragma unroll
    for (int j = 8; j < 16; j++) {
        ulonglong2 t = v[j];
        asm("fma.rn.f32x2 %0, %1, %2, %0;" : "+l"(a2) : "l"(t.x), "l"(w[2*j]));
        asm("fma.rn.f32x2 %0, %1, %2, %0;" : "+l"(a3) : "l"(t.y), "l"(w[2*j+1]));
    }
    uint64_t s01, s23, s;
    asm("add.rn.f32x2 %0, %1, %2;" : "=l"(s01) : "l"(a0), "l"(a1));
    asm("add.rn.f32x2 %0, %1, %2;" : "=l"(s23) : "l"(a2), "l"(a3));
    asm("add.rn.f32x2 %0, %1, %2;" : "=l"(s)   : "l"(s01), "l"(s23));
    float lo, hi;
    asm("mov.b64 {%0, %1}, %2;" : "=f"(lo), "=f"(hi) : "l"(s));
    return lo + hi;
}

__device__ __forceinline__ uint64_t pack2(float lo, float hi) {
    uint64_t r; asm("mov.b64 %0, {%1, %2};" : "=l"(r) : "f"(lo), "f"(hi)); return r;
}

__device__ __forceinline__ void mbar_wait(uint32_t mbar, uint32_t parity) {
    asm volatile(
        "{\n\t"
        ".reg .pred P;\n\t"
        "WAIT_%=:\n\t"
        "mbarrier.try_wait.parity.acquire.cluster.shared::cta.b64 P, [%0], %1, 10000000;\n\t"
        "@!P bra WAIT_%=;\n\t"
        "}"
        :: "r"(mbar), "r"(parity) : "memory");
}

// Remote (cluster) mbarrier arrive with release semantics: orders this warp's
// prior weak DSMEM stores (via the preceding __syncwarp) before the arrival.
__device__ __forceinline__ void mbar_arrive_remote(uint32_t mbar) {
    asm volatile("mbarrier.arrive.release.cluster.shared::cluster.b64 _, [%0];"
                 :: "r"(mbar) : "memory");
}

// Weak DSMEM v2 store into a peer CTA's shared memory.
__device__ __forceinline__ void st_cluster_v2(uint32_t addr, float x, float y) {
    asm volatile("st.shared::cluster.v2.f32 [%0], {%1, %2};"
                 :: "r"(addr), "f"(x), "f"(y) : "memory");
}

// ---------------------------------------------------------------------------
// Sequential MGRU scan — direct DSMEM v2 stores + 8 counted release-arrivals.
//
// 32 clusters x 4 CTAs, one cluster per batch row. CTA r owns state indices
// G = [64r, 64r+64) both as hidden columns and as k-rows of Uz/Uh. Thread
// tid (jp = tid) computes the k-partials over G:
//   pUh(t)   = sum_{k in G} a_k(t)   Uh[k,jp],  a(t)=z(t)(.)h(t-1)  LOCAL
//   pUz(t+1) = sum_{k in G} h_k(t-3) Uz[k,jp]   (shadow of step t; packet t+1
//              feeds z(t+2) which uses h(t+2-5)=h(t-3))
// Each thread writes {pUh, pUz} with ONE st.shared::cluster.v2.f32 into the
// owner CTA's inbox (no staging, no bulk engine). Warp w's 32 columns share
// one destination (w>>1); after __syncwarp, lane 0 release-arrives on the
// destination's mb[t&1]. Each barrier counts 8 arrivals (2 warps x 4 CTAs).
// Consumers (threads 0..63) acquire-wait, sum 4 partials, apply activations.
//
// Buffer-reuse safety (all chains go through the end-of-step __syncthreads):
//   a_loc[p]   read by dots at t; rewritten at update(t+1) (after sync(t)).
//   inbox[p]   read by owners at t (before sync(t)); peers rewrite at t+2,
//              which follows their wait(t+1) <- our arrive(t+1) <- sync(t).
//   hd_ring    slot s%5 written at update(s), shadow-read at t=s+3; the
//              shadow read of slot (t+2)%5 at t never collides with the
//              concurrent write of slot t%5.
//   mb phases  arrivals for phase(t+2) of mb[t&1] follow producers' wait(t+1)
//              <- our arrive(t+1) <- our sync(t) <- our wait(t) consumed it.
// ---------------------------------------------------------------------------
__global__ void __launch_bounds__(256, 1) __cluster_dims__(4, 1, 1)
mgru_scan(const float* __restrict__ xz, const float* __restrict__ xh,
          const float* __restrict__ Uz, const float* __restrict__ Uh,
          float* __restrict__ hs)
{
    __shared__ __align__(16) float a_loc[2][64];        // a(t) local chunk
    __shared__ __align__(16) float hd_ring[NDELAY][64]; // local h history
    __shared__ __align__(16) float inbox[2][512];       // [p][src*128+idx*2(+1)]
    __shared__ __align__(8) unsigned long long mb[2];

    const int rank = blockIdx.x & 3;
    const int b    = blockIdx.x >> 2;
    const int tid  = threadIdx.x;
    const int lane = tid & 31;
    const int jp   = tid;                 // partial column (global, 0..255)
    const int pr   = tid >> 6;            // destination CTA (owner of jp)
    const int idx  = tid & 63;            // index within destination slice

    // Register-resident weight slices: rows k in G, column jp.
    uint64_t wz2[32], wh2[32];
    {
        const float* uz = Uz + (size_t)(rank * 64) * Hsz + jp;
        const float* uh = Uh + (size_t)(rank * 64) * Hsz + jp;
#pragma unroll
        for (int i = 0; i < 32; i++) {
            wz2[i] = pack2(uz[(size_t)(2*i) * Hsz], uz[(size_t)(2*i+1) * Hsz]);
            wh2[i] = pack2(uh[(size_t)(2*i) * Hsz], uh[(size_t)(2*i+1) * Hsz]);
        }
    }

    if (tid == 0) {
        uint32_t m0 = (uint32_t)__cvta_generic_to_shared(&mb[0]);
        // 8 counted arrivals per phase: 2 producing warps x 4 source CTAs
        asm volatile("mbarrier.init.shared.b64 [%0], 8;" :: "r"(m0) : "memory");
        asm volatile("mbarrier.init.shared.b64 [%0], 8;" :: "r"(m0 + 8) : "memory");
    }
    for (int i = tid; i < 2 * 64;      i += 256) (&a_loc[0][0])[i]   = 0.f;
    for (int i = tid; i < NDELAY * 64; i += 256) (&hd_ring[0][0])[i] = 0.f;
    for (int i = tid; i < 2 * 512;     i += 256) (&inbox[0][0])[i]   = 0.f;
    __syncthreads();
    // all CTAs' mbarriers + zeroed buffers visible before any DSMEM traffic
    asm volatile("barrier.cluster.arrive.aligned;" ::: "memory");
    asm volatile("barrier.cluster.wait.aligned;" ::: "memory");

    const uint32_t inbox_sa = (uint32_t)__cvta_generic_to_shared(&inbox[0][0]);
    const uint32_t mb_sa    = (uint32_t)__cvta_generic_to_shared(&mb[0]);
    uint32_t peer_inbox = 0, peer_mb = 0;   // in CTA `pr`'s SMEM
    asm("mapa.shared::cluster.u32 %0, %1, %2;" : "=r"(peer_inbox) : "r"(inbox_sa), "r"(pr));
    asm("mapa.shared::cluster.u32 %0, %1, %2;" : "=r"(peer_mb)    : "r"(mb_sa),    "r"(pr));
    // destination slot for this thread's {pUh,pUz} pair (phase-invariant part)
    const uint32_t dst_base = peer_inbox + (uint32_t)(rank << 9) + (uint32_t)(idx << 3);

    // Column-owner state (threads 0..63): jglob = 64*rank + tid
    const int jglob = rank * 64 + tid;    // valid for tid < 64
    const float* xzp = xz + (size_t)b * Lsz * Hsz + jglob;
    const float* xhp = xh + (size_t)b * Lsz * Hsz + jglob;
    float*       hsp = hs + (size_t)b * Lsz * Hsz + jglob;

    float h = 0.f, z = 0.f;
    float xh_cur = 0.f, xz_nxt = 0.f, xh_nxt = 0.f;
    if (tid < 64) {
        xh_cur = xhp[0];
        xz_nxt = xzp[Hsz];
        xh_nxt = xhp[Hsz];
        z      = sigmoid_fast(xzp[0]);   // z(0): h(-5) = 0
        // a(0) = z(0)*h(-1) = 0 -> a_loc[0] already zeroed
    }

    float pUz_next = 0.f;   // packet 0 pUz: z(1) uses h(-4) = 0

    int slot_s = 2;  // (t+2)%5 : shadow-read h(t-3) for packet t+1
    int slot_w = 0;  // t%5     : write h(t)

    for (int t = 0; t < Lsz; ++t) {
        const int p = t & 1;
        const uint32_t boff = (uint32_t)(p << 3);

        // ---- Uh partial from the local a(t) chunk (critical path)
        float pUh = dot64_bcast(&a_loc[p][0], wh2);

        // ---- one weak DSMEM v2 store straight into the owner's inbox
        st_cluster_v2(dst_base + (uint32_t)(p << 11), pUh, pUz_next);
        __syncwarp();
        if (lane == 0) mbar_arrive_remote(peer_mb + boff);

        // ---- shadow: pUz for packet t+1 (h(t-3)); gmem prefetch
        float pUz_sh = dot64_bcast(&hd_ring[slot_s][0], wz2);
        float xz_p2 = 0.f, xh_p2 = 0.f;
        if (tid < 64 && t + 2 < Lsz) {
            xz_p2 = __ldg(xzp + (size_t)(t + 2) * Hsz);
            xh_p2 = __ldg(xhp + (size_t)(t + 2) * Hsz);
        }

        // ---- owners: acquire-wait for 8 arrivals, then reduce + update
        if (tid < 64) {
            if (lane == 0) mbar_wait(mb_sa + boff, (uint32_t)((t >> 1) & 1));
            __syncwarp();

            const float* ib = &inbox[p][0];
            float2 v0 = *(const float2*)&ib[      2 * tid];
            float2 v1 = *(const float2*)&ib[128 + 2 * tid];
            float2 v2 = *(const float2*)&ib[256 + 2 * tid];
            float2 v3 = *(const float2*)&ib[384 + 2 * tid];
            float sh = (v0.x + v1.x) + (v2.x + v3.x);
            float sz = (v0.y + v1.y) + (v2.y + v3.y);

            float ht = tanh_fast(sh + xh_cur);
            h = h + z * (ht - h);                  // h(t)
            float zn = sigmoid_fast(sz + xz_nxt);  // z(t+1)

            a_loc[p ^ 1][tid]    = zn * h;         // a(t+1) local chunk
            hd_ring[slot_w][tid] = h;              // h(t) into ring
            hsp[(size_t)t * Hsz] = h;

            z = zn;
            xh_cur = xh_nxt;
            xz_nxt = xz_p2;
            xh_nxt = xh_p2;
        }
        __syncthreads();

        pUz_next = pUz_sh;
        slot_s = (slot_s == NDELAY - 1) ? 0 : slot_s + 1;
        slot_w = (slot_w == NDELAY - 1) ? 0 : slot_w + 1;
    }

    // no CTA may exit while peer traffic targeting it may be in flight
    asm volatile("barrier.cluster.arrive.aligned;" ::: "memory");
    asm volatile("barrier.cluster.wait.aligned;" ::: "memory");
}

// Dummy so ncu (6th global launch; 2 harness launches precede ours) captures
// the scan.
__global__ void dummy_k() {}

// ---------------------------------------------------------------------------
// Launch: proj GEMMs -> dummy -> scan -> head GEMM
// ---------------------------------------------------------------------------
extern "C" void kernel_launch(void* const* d_in, const int* in_sizes, int n_in,
                              void* d_out, int out_size)
{
    const float* x  = (const float*)d_in[0];
    const float* Wz = (const float*)d_in[1];
    const float* Uz = (const float*)d_in[2];
    const float* bz = (const float*)d_in[3];
    const float* Wh = (const float*)d_in[4];
    const float* Uh = (const float*)d_in[5];
    const float* bh = (const float*)d_in[6];
    const float* Wo = (const float*)d_in[7];
    const float* bo = (const float*)d_in[8];
    float* y = (float*)d_out;

    float *xz_p = nullptr, *xh_p = nullptr, *hs_p = nullptr;
    cudaGetSymbolAddress((void**)&xz_p, g_xz);
    cudaGetSymbolAddress((void**)&xh_p, g_xh);
    cudaGetSymbolAddress((void**)&hs_p, g_hs);

    const int M = Bsz * Lsz;           // 131072
    dim3 blk(256);

    gemm_bias<<<dim3(M / 64, Hsz / 64), blk>>>(x, Wz, bz, xz_p, M, Isz, Hsz);
    gemm_bias<<<dim3(M / 64, Hsz / 64), blk>>>(x, Wh, bh, xh_p, M, Isz, Hsz);

    dummy_k<<<1, 1>>>();

    mgru_scan<<<Bsz * 4, 256>>>(xz_p, xh_p, Uz, Uh, hs_p);

    gemm_bias<<<dim3(M / 64, Osz / 64), blk>>>(hs_p, Wo, bo, y, M, Hsz, Osz);
}

// round 13
// speedup vs baseline: 1.1673x; 1.1673x over previous
#include <cuda_runtime.h>
#include <cstdint>

// Problem constants
#define Bsz 32
#define Lsz 4096
#define Isz 128
#define Hsz 256
#define Osz 128
#define NDELAY 5      // delay line length (DELAY+1)

// Scratch (static device globals: allocation-free per harness rules)
__device__ float g_xz[Bsz * Lsz * Hsz];
__device__ float g_xh[Bsz * Lsz * Hsz];
__device__ float g_hs[Bsz * Lsz * Hsz];

// ---------------------------------------------------------------------------
// fp32 tiled GEMM with bias, packed f32x2 accumulation.
// C[M,N] = A[M,K] @ B[K,N] + bias[N]; 64x64 tile, 256 threads, 4x4 micro.
// ---------------------------------------------------------------------------
__global__ void __launch_bounds__(256) gemm_bias(
    const float* __restrict__ A, const float* __restrict__ Bm,
    const float* __restrict__ bias, float* __restrict__ C,
    int M, int K, int N)
{
    __shared__ float sA[64][68];
    __shared__ float sB[64][68];

    const int m0  = blockIdx.x << 6;
    const int n0  = blockIdx.y << 6;
    const int tid = threadIdx.x;
    const int tx  = tid & 15;
    const int ty  = tid >> 4;

    uint64_t acc01[4], acc23[4];   // packed (col0,col1) / (col2,col3) per row
#pragma unroll
    for (int i = 0; i < 4; i++) { acc01[i] = 0; acc23[i] = 0; }

    for (int kk = 0; kk < K; kk += 64) {
#pragma unroll
        for (int i = 0; i < 4; i++) {
            int lin = tid + (i << 8);
            int r   = lin >> 4;
            int c   = (lin & 15) << 2;
            *(float4*)&sA[r][c] = *(const float4*)&A[(size_t)(m0 + r) * K + kk + c];
            *(float4*)&sB[r][c] = *(const float4*)&Bm[(size_t)(kk + r) * N + n0 + c];
        }
        __syncthreads();

#pragma unroll 16
        for (int k = 0; k < 64; k++) {
            ulonglong2 bb = *(const ulonglong2*)&sB[k][tx << 2];
#pragma unroll
            for (int i = 0; i < 4; i++) {
                float a = sA[(ty << 2) + i][k];
                uint64_t aa;
                asm("mov.b64 %0, {%1, %1};" : "=l"(aa) : "f"(a));
                asm("fma.rn.f32x2 %0, %1, %2, %0;" : "+l"(acc01[i]) : "l"(aa), "l"(bb.x));
                asm("fma.rn.f32x2 %0, %1, %2, %0;" : "+l"(acc23[i]) : "l"(aa), "l"(bb.y));
            }
        }
        __syncthreads();
    }

    float4 bb = *(const float4*)&bias[n0 + (tx << 2)];
#pragma unroll
    for (int i = 0; i < 4; i++) {
        float c0, c1, c2, c3;
        asm("mov.b64 {%0, %1}, %2;" : "=f"(c0), "=f"(c1) : "l"(acc01[i]));
        asm("mov.b64 {%0, %1}, %2;" : "=f"(c2), "=f"(c3) : "l"(acc23[i]));
        float4 o;
        o.x = c0 + bb.x; o.y = c1 + bb.y; o.z = c2 + bb.z; o.w = c3 + bb.w;
        *(float4*)&C[(size_t)(m0 + (ty << 2) + i) * N + n0 + (tx << 2)] = o;
    }
}

// ---------------------------------------------------------------------------
// Fast-math helpers (ex2/rcp approx: rel err ~1e-7)
// ---------------------------------------------------------------------------
__device__ __forceinline__ float ex2_fast(float x) {
    float r; asm("ex2.approx.f32 %0, %1;" : "=f"(r) : "f"(x)); return r;
}
__device__ __forceinline__ float rcp_fast(float x) {
    float r; asm("rcp.approx.f32 %0, %1;" : "=f"(r) : "f"(x)); return r;
}
__device__ __forceinline__ float sigmoid_fast(float x) {
    return rcp_fast(1.f + ex2_fast(-1.4426950408889634f * x));
}
__device__ __forceinline__ float tanh_fast(float x) {
    float e = ex2_fast(2.885390081777927f * x);
    return (e - 1.f) * rcp_fast(e + 1.f);
}

// Packed f32x2 dot over 64 floats; all lanes read the SAME addresses
// (whole-warp broadcast -> conflict-free, 1 wavefront per LDS.128).
__device__ __forceinline__ float dot64_bcast(const float* p, const uint64_t* w) {
    const ulonglong2* v = (const ulonglong2*)p;
    uint64_t a0 = 0, a1 = 0, a2 = 0, a3 = 0;
#pragma unroll
    for (int j = 0; j < 8; j++) {
        ulonglong2 t = v[j];
        asm("fma.rn.f32x2 %0, %1, %2, %0;" : "+l"(a0) : "l"(t.x), "l"(w[2*j]));
        asm("fma.rn.f32x2 %0, %1, %2, %0;" : "+l"(a1) : "l"(t.y), "l"(w[2*j+1]));
    }
#pragma unroll
    for (int j = 8; j < 16; j++) {
        ulonglong2 t = v[j];
        asm("fma.rn.f32x2 %0, %1, %2, %0;" : "+l"(a2) : "l"(t.x), "l"(w[2*j]));
        asm("fma.rn.f32x2 %0, %1, %2, %0;" : "+l"(a3) : "l"(t.y), "l"(w[2*j+1]));
    }
    uint64_t s01, s23, s;
    asm("add.rn.f32x2 %0, %1, %2;" : "=l"(s01) : "l"(a0), "l"(a1));
    asm("add.rn.f32x2 %0, %1, %2;" : "=l"(s23) : "l"(a2), "l"(a3));
    asm("add.rn.f32x2 %0, %1, %2;" : "=l"(s)   : "l"(s01), "l"(s23));
    float lo, hi;
    asm("mov.b64 {%0, %1}, %2;" : "=f"(lo), "=f"(hi) : "l"(s));
    return lo + hi;
}

__device__ __forceinline__ uint64_t pack2(float lo, float hi) {
    uint64_t r; asm("mov.b64 %0, {%1, %2};" : "=l"(r) : "f"(lo), "f"(hi)); return r;
}

__device__ __forceinline__ void mbar_expect_tx(uint32_t mbar, uint32_t bytes) {
    asm volatile("mbarrier.arrive.expect_tx.shared.b64 _, [%0], %1;"
                 :: "r"(mbar), "r"(bytes) : "memory");
}

__device__ __forceinline__ void mbar_wait(uint32_t mbar, uint32_t parity) {
    asm volatile(
        "{\n\t"
        ".reg .pred P;\n\t"
        "WAIT_%=:\n\t"
        "mbarrier.try_wait.parity.acquire.cluster.shared::cta.b64 P, [%0], %1, 10000000;\n\t"
        "@!P bra WAIT_%=;\n\t"
        "}"
        :: "r"(mbar), "r"(parity) : "memory");
}

// DSMEM bulk copy: local smem -> peer smem, complete_tx to peer's mbarrier.
__device__ __forceinline__ void bulk_s2s(uint32_t dst, uint32_t src,
                                         uint32_t bytes, uint32_t mbar) {
    asm volatile(
        "cp.async.bulk.shared::cluster.shared::cta.mbarrier::complete_tx::bytes "
        "[%0], [%1], %2, [%3];"
        :: "r"(dst), "r"(src), "r"(bytes), "r"(mbar) : "memory");
}

__device__ __forceinline__ void fence_async() {
    asm volatile("fence.proxy.async.shared::cta;" ::: "memory");
}

// ---------------------------------------------------------------------------
// Sequential MGRU scan — warp-autonomous 256B bulk pushes + shadowed Uz dot.
//
// 32 clusters x 4 CTAs, one cluster per batch row. CTA r owns state indices
// G = [64r, 64r+64) both as hidden columns and as k-rows of Uz/Uh. Thread
// tid (jp = tid) computes the k-partials over G:
//   pUh(t)   = sum_{k in G} a_k(t)   Uh[k,jp],  a(t)=z(t)(.)h(t-1)  LOCAL
//   pUz(t+1) = sum_{k in G} h_k(t-3) Uz[k,jp]   (computed in step t's shadow;
//              packet t+1 feeds z(t+2) which uses h(t+2-5)=h(t-3))
// Warp w covers columns 32w..32w+31, all owned by destination CTA d=w>>1,
// half hf=w&1. Each thread STS's its {pUh, pUz_next} pair into the warp's
// contiguous 256B stage block; after __syncwarp, lane 0 bulk-pushes that
// block into the owner's inbox. Per destination: 8 copies x 256B = 2048
// tx-bytes on mb[t&1]. NO full-CTA sync before the push.
//
// Buffer-reuse safety (chains via end-of-step __syncthreads + wait-chain):
//   a_loc[p]   read by every warp's dot(t) (all before end-sync(t));
//              rewritten at update(t+1), which follows wait(t+1) <- all 8
//              warps' pushes(t+1) <- end-sync(t).
//   stage[p]   engine-read at push(t) (completes before peer wait(t));
//              rewritten at t+2 after our wait(t+1) <- peer push(t+1)
//              <- peer end-sync(t) <- peer wait(t) <- our tx arrived.
//   inbox[p]   owner-read at t (before end-sync(t)); peer overwrite at t+2
//              follows peer wait(t+1) <- our pushes(t+1) <- our end-sync(t).
//   hd_ring    slot s%5 written at update(s); shadow-read at t reads slot
//              (t+2)%5 = h(t-3) (3 syncs of slack; never the slot t%5 being
//              written concurrently).
//   mb[p]      arrivals for phase t+2 follow producers' end-sync(t+1), after
//              the phase-t wait consumed the barrier.
// ---------------------------------------------------------------------------
__global__ void __launch_bounds__(256, 1) __cluster_dims__(4, 1, 1)
mgru_scan(const float* __restrict__ xz, const float* __restrict__ xh,
          const float* __restrict__ Uz, const float* __restrict__ Uh,
          float* __restrict__ hs)
{
    __shared__ __align__(16) float a_loc[2][64];        // a(t) local chunk
    __shared__ __align__(16) float hd_ring[NDELAY][64]; // local h history
    __shared__ __align__(16) float stage[2][512];       // [p][warp*64 + 2*lane]
    __shared__ __align__(16) float inbox[2][512];       // [p][src*128 + 2*idx]
    __shared__ __align__(8) unsigned long long mb[2];

    const int rank = blockIdx.x & 3;
    const int b    = blockIdx.x >> 2;
    const int tid  = threadIdx.x;
    const int lane = tid & 31;
    const int wid  = tid >> 5;            // warp 0..7
    const int d    = wid >> 1;            // destination CTA of this warp's cols
    const int hf   = wid & 1;             // which half of the dest's slice
    const int jp   = tid;                 // partial column (global, 0..255)

    // Register-resident weight slices: rows k in G, column jp.
    uint64_t wz2[32], wh2[32];
    {
        const float* uz = Uz + (size_t)(rank * 64) * Hsz + jp;
        const float* uh = Uh + (size_t)(rank * 64) * Hsz + jp;
#pragma unroll
        for (int i = 0; i < 32; i++) {
            wz2[i] = pack2(uz[(size_t)(2*i) * Hsz], uz[(size_t)(2*i+1) * Hsz]);
            wh2[i] = pack2(uh[(size_t)(2*i) * Hsz], uh[(size_t)(2*i+1) * Hsz]);
        }
    }

    if (tid == 0) {
        uint32_t m0 = (uint32_t)__cvta_generic_to_shared(&mb[0]);
        asm volatile("mbarrier.init.shared.b64 [%0], 1;" :: "r"(m0) : "memory");
        asm volatile("mbarrier.init.shared.b64 [%0], 1;" :: "r"(m0 + 8) : "memory");
    }
    for (int i = tid; i < 2 * 64;      i += 256) (&a_loc[0][0])[i]   = 0.f;
    for (int i = tid; i < NDELAY * 64; i += 256) (&hd_ring[0][0])[i] = 0.f;
    for (int i = tid; i < 2 * 512;     i += 256) (&stage[0][0])[i]   = 0.f;
    for (int i = tid; i < 2 * 512;     i += 256) (&inbox[0][0])[i]   = 0.f;
    __syncthreads();
    // all CTAs' mbarriers + zeroed buffers visible before any DSMEM traffic
    asm volatile("barrier.cluster.arrive.aligned;" ::: "memory");
    asm volatile("barrier.cluster.wait.aligned;" ::: "memory");

    const uint32_t stage_sa = (uint32_t)__cvta_generic_to_shared(&stage[0][0]);
    const uint32_t inbox_sa = (uint32_t)__cvta_generic_to_shared(&inbox[0][0]);
    const uint32_t mb_sa    = (uint32_t)__cvta_generic_to_shared(&mb[0]);
    uint32_t peer_inbox = 0, peer_mb = 0;   // in CTA `d`'s SMEM (per warp)
    asm("mapa.shared::cluster.u32 %0, %1, %2;" : "=r"(peer_inbox) : "r"(inbox_sa), "r"(d));
    asm("mapa.shared::cluster.u32 %0, %1, %2;" : "=r"(peer_mb)    : "r"(mb_sa),    "r"(d));
    // this warp's 256B stage block and its destination block (phase-invariant)
    const uint32_t src_base = stage_sa + (uint32_t)(wid << 8);
    const uint32_t dst_base = peer_inbox + (uint32_t)((rank * 128 + hf * 64) << 2);

    // Column-owner state (threads 0..63): jglob = 64*rank + tid
    const int jglob = rank * 64 + tid;    // valid for tid < 64
    const float* xzp = xz + (size_t)b * Lsz * Hsz + jglob;
    const float* xhp = xh + (size_t)b * Lsz * Hsz + jglob;
    float*       hsp = hs + (size_t)b * Lsz * Hsz + jglob;

    float h = 0.f, z = 0.f;
    float xh_cur = 0.f, xz_nxt = 0.f, xh_nxt = 0.f;
    if (tid < 64) {
        xh_cur = xhp[0];
        xz_nxt = xzp[Hsz];
        xh_nxt = xhp[Hsz];
        z      = sigmoid_fast(xzp[0]);   // z(0): h(-5) = 0
        // a(0) = z(0)*h(-1) = 0 -> a_loc[0] already zeroed
    }

    float pUz_next = 0.f;   // packet 0 pUz: z(1) uses h(-4) = 0

    int slot_s = 2;  // (t+2)%5 : shadow-read h(t-3) for packet t+1
    int slot_w = 0;  // t%5     : write h(t)

    for (int t = 0; t < Lsz; ++t) {
        const int p = t & 1;
        const uint32_t boff = (uint32_t)(p << 3);
        const uint32_t pb   = (uint32_t)(p << 11);   // p*512 floats in bytes

        // ---- Uh partial from the local a(t) chunk (critical path)
        float pUh = dot64_bcast(&a_loc[p][0], wh2);

        // ---- stage own {pUh, pUz} pair; warp-autonomous 256B push
        *(float2*)&stage[p][(wid << 6) + (lane << 1)] = make_float2(pUh, pUz_next);
        __syncwarp();
        if (lane == 0) {
            fence_async();
            bulk_s2s(dst_base + pb, src_base + pb, 256u, peer_mb + boff);
        }
        if (tid == 0) mbar_expect_tx(mb_sa + boff, 2048u);

        // ---- shadow: pUz for packet t+1 (h(t-3)); gmem prefetch
        float pUz_sh = dot64_bcast(&hd_ring[slot_s][0], wz2);
        float xz_p2 = 0.f, xh_p2 = 0.f;
        if (tid < 64 && t + 2 < Lsz) {
            xz_p2 = __ldg(xzp + (size_t)(t + 2) * Hsz);
            xh_p2 = __ldg(xhp + (size_t)(t + 2) * Hsz);
        }

        // ---- owners: acquire-wait, reduce 4 partial pairs, update state
        if (tid < 64) {
            if (lane == 0) mbar_wait(mb_sa + boff, (uint32_t)((t >> 1) & 1));
            __syncwarp();

            const float* ib = &inbox[p][0];
            float2 v0 = *(const float2*)&ib[      2 * tid];
            float2 v1 = *(const float2*)&ib[128 + 2 * tid];
            float2 v2 = *(const float2*)&ib[256 + 2 * tid];
            float2 v3 = *(const float2*)&ib[384 + 2 * tid];
            float sh = (v0.x + v1.x) + (v2.x + v3.x);
            float sz = (v0.y + v1.y) + (v2.y + v3.y);

            float ht = tanh_fast(sh + xh_cur);
            h = h + z * (ht - h);                  // h(t)
            float zn = sigmoid_fast(sz + xz_nxt);  // z(t+1)

            a_loc[p ^ 1][tid]    = zn * h;         // a(t+1) local chunk
            hd_ring[slot_w][tid] = h;              // h(t) into ring
            hsp[(size_t)t * Hsz] = h;

            z = zn;
            xh_cur = xh_nxt;
            xz_nxt = xz_p2;
            xh_nxt = xh_p2;
        }
        __syncthreads();

        pUz_next = pUz_sh;
        slot_s = (slot_s == NDELAY - 1) ? 0 : slot_s + 1;
        slot_w = (slot_w == NDELAY - 1) ? 0 : slot_w + 1;
    }

    // no CTA may exit while peer traffic targeting it may be in flight
    asm volatile("barrier.cluster.arrive.aligned;" ::: "memory");
    asm volatile("barrier.cluster.wait.aligned;" ::: "memory");
}

// Dummy so ncu (6th global launch; 2 harness launches precede ours) captures
// the scan.
__global__ void dummy_k() {}

// ---------------------------------------------------------------------------
// Launch: proj GEMMs -> dummy -> scan -> head GEMM
// ---------------------------------------------------------------------------
extern "C" void kernel_launch(void* const* d_in, const int* in_sizes, int n_in,
                              void* d_out, int out_size)
{
    const float* x  = (const float*)d_in[0];
    const float* Wz = (const float*)d_in[1];
    const float* Uz = (const float*)d_in[2];
    const float* bz = (const float*)d_in[3];
    const float* Wh = (const float*)d_in[4];
    const float* Uh = (const float*)d_in[5];
    const float* bh = (const float*)d_in[6];
    const float* Wo = (const float*)d_in[7];
    const float* bo = (const float*)d_in[8];
    float* y = (float*)d_out;

    float *xz_p = nullptr, *xh_p = nullptr, *hs_p = nullptr;
    cudaGetSymbolAddress((void**)&xz_p, g_xz);
    cudaGetSymbolAddress((void**)&xh_p, g_xh);
    cudaGetSymbolAddress((void**)&hs_p, g_hs);

    const int M = Bsz * Lsz;           // 131072
    dim3 blk(256);

    gemm_bias<<<dim3(M / 64, Hsz / 64), blk>>>(x, Wz, bz, xz_p, M, Isz, Hsz);
    gemm_bias<<<dim3(M / 64, Hsz / 64), blk>>>(x, Wh, bh, xh_p, M, Isz, Hsz);

    dummy_k<<<1, 1>>>();

    mgru_scan<<<Bsz * 4, 256>>>(xz_p, xh_p, Uz, Uh, hs_p);

    gemm_bias<<<dim3(M / 64, Osz / 64), blk>>>(hs_p, Wo, bo, y, M, Hsz, Osz);
}